// round 2
// baseline (speedup 1.0000x reference)
#include <cuda_runtime.h>
#include <cuda_bf16.h>
#include <math.h>

#define EMB 1024
#define HEADS 16
#define LAT 256
#define FFN 4096
#define HD 64
#define BATCH 2
#define SEQ 2048
#define M_TOK (BATCH * SEQ)   // 4096 rows

// ---------------- scratch (device globals; no allocation allowed) ----------
__device__ float g_Q [M_TOK * EMB];
__device__ float g_Ka[M_TOK * LAT];
__device__ float g_K [M_TOK * EMB];
__device__ float g_Va[M_TOK * LAT];
__device__ float g_V [M_TOK * EMB];
__device__ float g_At[M_TOK * EMB];   // attention context
__device__ float g_AO[M_TOK * EMB];   // after Wo
__device__ float g_H [M_TOK * EMB];   // after LN1
__device__ float g_F1[M_TOK * FFN];
__device__ float g_F2[M_TOK * EMB];

// ---------------- generic tiled GEMM: C = act(A @ W + bias) ----------------
// A: MxK row-major, W: KxN row-major, C: MxN. All dims multiples of tile.
#define BM 64
#define BN 64
#define BK 16

__device__ __forceinline__ float gelu_exact(float x) {
    return 0.5f * x * (1.0f + erff(x * 0.70710678118654752f));
}

__global__ __launch_bounds__(256)
void gemm_bias_act(const float* __restrict__ A, const float* __restrict__ W,
                   const float* __restrict__ bias, float* __restrict__ C,
                   int M, int Ncols, int K, int act)
{
    __shared__ float As[BM][BK + 1];
    __shared__ float Bs[BK][BN];

    const int tid = threadIdx.x;
    const int tx = tid & 15;
    const int ty = tid >> 4;
    const int row0 = blockIdx.y * BM;
    const int col0 = blockIdx.x * BN;

    float acc[4][4];
#pragma unroll
    for (int i = 0; i < 4; i++)
#pragma unroll
        for (int j = 0; j < 4; j++) acc[i][j] = 0.f;

    for (int k0 = 0; k0 < K; k0 += BK) {
        // A tile 64x16: 256 threads, one float4 each
        {
            int r = tid >> 2;
            int c = (tid & 3) << 2;
            float4 v = *(const float4*)(A + (size_t)(row0 + r) * K + k0 + c);
            As[r][c + 0] = v.x; As[r][c + 1] = v.y;
            As[r][c + 2] = v.z; As[r][c + 3] = v.w;
        }
        // W tile 16x64: 256 threads, one float4 each
        {
            int r = tid >> 4;
            int c = (tid & 15) << 2;
            float4 v = *(const float4*)(W + (size_t)(k0 + r) * Ncols + col0 + c);
            *(float4*)&Bs[r][c] = v;
        }
        __syncthreads();

#pragma unroll
        for (int k = 0; k < BK; k++) {
            float a[4], b[4];
#pragma unroll
            for (int i = 0; i < 4; i++) a[i] = As[ty * 4 + i][k];
#pragma unroll
            for (int j = 0; j < 4; j++) b[j] = Bs[k][tx * 4 + j];
#pragma unroll
            for (int i = 0; i < 4; i++)
#pragma unroll
                for (int j = 0; j < 4; j++) acc[i][j] += a[i] * b[j];
        }
        __syncthreads();
    }

#pragma unroll
    for (int i = 0; i < 4; i++) {
        int r = row0 + ty * 4 + i;
#pragma unroll
        for (int j = 0; j < 4; j++) {
            int c = col0 + tx * 4 + j;
            float v = acc[i][j] + bias[c];
            if (act) v = gelu_exact(v);
            C[(size_t)r * Ncols + c] = v;
        }
    }
}

// ---------------- flash attention ------------------------------------------
// grid: (SEQ/BR, BATCH*HEADS), block: BR threads (one per query row)
#define BR 64
#define BC 64

__global__ __launch_bounds__(64)
void attn_kernel(const float* __restrict__ Q, const float* __restrict__ K,
                 const float* __restrict__ V, const float* __restrict__ bias,
                 float* __restrict__ O)
{
    __shared__ float Ks[BC][HD];
    __shared__ float Vs[BC][HD];
    __shared__ float Bsm[BC][BR];   // transposed bias tile: [key][query]

    const int bh = blockIdx.y;
    const int b  = bh / HEADS;
    const int h  = bh % HEADS;
    const int q0 = blockIdx.x * BR;
    const int t  = threadIdx.x;          // query row within tile

    const float* qptr = Q + ((size_t)b * SEQ + q0 + t) * EMB + h * HD;
    float q[HD], o[HD];
#pragma unroll
    for (int d = 0; d < HD; d++) { q[d] = qptr[d] * 0.125f; o[d] = 0.f; }

    float m = -1e30f, l = 0.f;

    for (int k0 = 0; k0 < SEQ; k0 += BC) {
        __syncthreads();
        // K/V tiles: BC*HD floats each; 64 threads x 16 float4
        for (int i = t; i < BC * HD / 4; i += BR) {
            int r = i / (HD / 4);
            int c = i % (HD / 4);
            const float4* kp = (const float4*)(K + ((size_t)b * SEQ + k0 + r) * EMB + h * HD);
            const float4* vp = (const float4*)(V + ((size_t)b * SEQ + k0 + r) * EMB + h * HD);
            ((float4*)Ks[r])[c] = kp[c];
            ((float4*)Vs[r])[c] = vp[c];
        }
        // bias tile (transposed store)
        for (int i = t; i < BR * BC / 4; i += BR) {
            int r = i / (BC / 4);           // query row in tile
            int c = (i % (BC / 4)) * 4;     // key col in tile
            float4 v = *(const float4*)(bias + (size_t)(q0 + r) * SEQ + k0 + c);
            Bsm[c + 0][r] = v.x; Bsm[c + 1][r] = v.y;
            Bsm[c + 2][r] = v.z; Bsm[c + 3][r] = v.w;
        }
        __syncthreads();

        // pass 1: scores (write back into Bsm), running max
        float mnew = m;
#pragma unroll 2
        for (int j = 0; j < BC; j++) {
            float acc = Bsm[j][t];
#pragma unroll
            for (int d = 0; d < HD; d++) acc += q[d] * Ks[j][d];
            Bsm[j][t] = acc;
            mnew = fmaxf(mnew, acc);
        }

        float corr = __expf(m - mnew);
        m = mnew;
        l *= corr;
#pragma unroll
        for (int d = 0; d < HD; d++) o[d] *= corr;

        // pass 2: weights + AV accumulate
#pragma unroll 2
        for (int j = 0; j < BC; j++) {
            float p = __expf(Bsm[j][t] - m);
            l += p;
#pragma unroll
            for (int d = 0; d < HD; d++) o[d] += p * Vs[j][d];
        }
    }

    float inv = 1.f / l;
    float* op = O + ((size_t)b * SEQ + q0 + t) * EMB + h * HD;
#pragma unroll
    for (int d = 0; d < HD; d++) op[d] = o[d] * inv;
}

// ---------------- fused residual add + LayerNorm ---------------------------
// grid: M_TOK blocks, 256 threads; row length EMB=1024 (4 per thread)
__global__ __launch_bounds__(256)
void add_ln_kernel(const float* __restrict__ X, const float* __restrict__ R,
                   const float* __restrict__ w, const float* __restrict__ bias,
                   float* __restrict__ Y)
{
    __shared__ float red[32];
    const int row = blockIdx.x;
    const int tid = threadIdx.x;
    const float* xr = X + (size_t)row * EMB;
    const float* rr = R + (size_t)row * EMB;

    float v[4];
    float s = 0.f;
#pragma unroll
    for (int i = 0; i < 4; i++) {
        int c = i * 256 + tid;
        v[i] = xr[c] + rr[c];
        s += v[i];
    }
    // block reduce sum
#pragma unroll
    for (int o = 16; o; o >>= 1) s += __shfl_xor_sync(0xffffffffu, s, o);
    if ((tid & 31) == 0) red[tid >> 5] = s;
    __syncthreads();
    if (tid < 32) {
        float r = (tid < 8) ? red[tid] : 0.f;
#pragma unroll
        for (int o = 4; o; o >>= 1) r += __shfl_xor_sync(0xffffffffu, r, o);
        if (tid == 0) red[0] = r;
    }
    __syncthreads();
    const float mu = red[0] * (1.0f / EMB);

    float vs = 0.f;
#pragma unroll
    for (int i = 0; i < 4; i++) {
        float d = v[i] - mu;
        vs += d * d;
    }
#pragma unroll
    for (int o = 16; o; o >>= 1) vs += __shfl_xor_sync(0xffffffffu, vs, o);
    __syncthreads();
    if ((tid & 31) == 0) red[tid >> 5] = vs;
    __syncthreads();
    if (tid < 32) {
        float r = (tid < 8) ? red[tid] : 0.f;
#pragma unroll
        for (int o = 4; o; o >>= 1) r += __shfl_xor_sync(0xffffffffu, r, o);
        if (tid == 0) red[0] = r;
    }
    __syncthreads();
    const float inv = rsqrtf(red[0] * (1.0f / EMB) + 1e-5f);

#pragma unroll
    for (int i = 0; i < 4; i++) {
        int c = i * 256 + tid;
        Y[(size_t)row * EMB + c] = (v[i] - mu) * inv * w[c] + bias[c];
    }
}

// ---------------- launch ----------------------------------------------------
static float* sym(const void* s) {
    void* p = nullptr;
    cudaGetSymbolAddress(&p, s);
    return (float*)p;
}

extern "C" void kernel_launch(void* const* d_in, const int* in_sizes, int n_in,
                              void* d_out, int out_size)
{
    (void)in_sizes; (void)n_in; (void)out_size;
    const float* x    = (const float*)d_in[0];
    const float* ab   = (const float*)d_in[1];
    const float* Wq   = (const float*)d_in[2];
    const float* bq   = (const float*)d_in[3];
    const float* WaK  = (const float*)d_in[4];
    const float* baK  = (const float*)d_in[5];
    const float* WbK  = (const float*)d_in[6];
    const float* bbK  = (const float*)d_in[7];
    const float* WaV  = (const float*)d_in[8];
    const float* baV  = (const float*)d_in[9];
    const float* WbV  = (const float*)d_in[10];
    const float* bbV  = (const float*)d_in[11];
    const float* Wo   = (const float*)d_in[12];
    const float* bo   = (const float*)d_in[13];
    const float* W1   = (const float*)d_in[14];
    const float* b1   = (const float*)d_in[15];
    const float* W2   = (const float*)d_in[16];
    const float* b2   = (const float*)d_in[17];
    const float* ln1w = (const float*)d_in[18];
    const float* ln1b = (const float*)d_in[19];
    const float* ln2w = (const float*)d_in[20];
    const float* ln2b = (const float*)d_in[21];
    float* out = (float*)d_out;

    float* Q  = sym(g_Q);  float* Ka = sym(g_Ka); float* K  = sym(g_K);
    float* Va = sym(g_Va); float* V  = sym(g_V);  float* At = sym(g_At);
    float* AO = sym(g_AO); float* H  = sym(g_H);
    float* F1 = sym(g_F1); float* F2 = sym(g_F2);

    dim3 blk(256);
    auto grid = [](int Nc, int M) { return dim3(Nc / BN, M / BM); };

    // projections
    gemm_bias_act<<<grid(EMB, M_TOK), blk>>>(x,  Wq,  bq,  Q,  M_TOK, EMB, EMB, 0);
    gemm_bias_act<<<grid(LAT, M_TOK), blk>>>(x,  WaK, baK, Ka, M_TOK, LAT, EMB, 0);
    gemm_bias_act<<<grid(EMB, M_TOK), blk>>>(Ka, WbK, bbK, K,  M_TOK, EMB, LAT, 0);
    gemm_bias_act<<<grid(LAT, M_TOK), blk>>>(x,  WaV, baV, Va, M_TOK, LAT, EMB, 0);
    gemm_bias_act<<<grid(EMB, M_TOK), blk>>>(Va, WbV, bbV, V,  M_TOK, EMB, LAT, 0);

    // attention
    attn_kernel<<<dim3(SEQ / BR, BATCH * HEADS), dim3(BR)>>>(Q, K, V, ab, At);

    // output projection + LN1
    gemm_bias_act<<<grid(EMB, M_TOK), blk>>>(At, Wo, bo, AO, M_TOK, EMB, EMB, 0);
    add_ln_kernel<<<M_TOK, blk>>>(x, AO, ln1w, ln1b, H);

    // FFN + LN2
    gemm_bias_act<<<grid(FFN, M_TOK), blk>>>(H,  W1, b1, F1, M_TOK, FFN, EMB, 1);
    gemm_bias_act<<<grid(EMB, M_TOK), blk>>>(F1, W2, b2, F2, M_TOK, EMB, FFN, 0);
    add_ln_kernel<<<M_TOK, blk>>>(H, F2, ln2w, ln2b, out);
}

// round 7
// speedup vs baseline: 1.5036x; 1.5036x over previous
#include <cuda_runtime.h>
#include <cuda_bf16.h>
#include <cstdint>
#include <math.h>

#define EMB 1024
#define HEADS 16
#define LAT 256
#define FFN 4096
#define HD 64
#define BATCH 2
#define SEQ 2048
#define M_TOK (BATCH * SEQ)   // 4096 rows

// ===================== scratch (device globals) =============================
__device__ float g_Q [M_TOK * EMB];
__device__ float g_Ka[M_TOK * LAT];
__device__ float g_K [M_TOK * EMB];
__device__ float g_Va[M_TOK * LAT];
__device__ float g_V [M_TOK * EMB];
__device__ float g_At[M_TOK * EMB];
__device__ float g_AO[M_TOK * EMB];
__device__ float g_H [M_TOK * EMB];
__device__ float g_F1[(size_t)M_TOK * FFN];
__device__ float g_F2[M_TOK * EMB];

// bf16 split buffers: activations [M, 3K] = [hi|hi|lo]
__device__ __nv_bfloat16 g_Xb [(size_t)M_TOK * 3 * EMB];
__device__ __nv_bfloat16 g_Kab[(size_t)M_TOK * 3 * LAT];
__device__ __nv_bfloat16 g_Vab[(size_t)M_TOK * 3 * LAT];
__device__ __nv_bfloat16 g_Atb[(size_t)M_TOK * 3 * EMB];
__device__ __nv_bfloat16 g_Hb [(size_t)M_TOK * 3 * EMB];
__device__ __nv_bfloat16 g_F1b[(size_t)M_TOK * 3 * FFN];
// weights transposed+split: [N, 3K] = [hi|lo|hi]
__device__ __nv_bfloat16 g_WqT [(size_t)EMB * 3 * EMB];
__device__ __nv_bfloat16 g_WaKT[(size_t)LAT * 3 * EMB];
__device__ __nv_bfloat16 g_WbKT[(size_t)EMB * 3 * LAT];
__device__ __nv_bfloat16 g_WaVT[(size_t)LAT * 3 * EMB];
__device__ __nv_bfloat16 g_WbVT[(size_t)EMB * 3 * LAT];
__device__ __nv_bfloat16 g_WoT [(size_t)EMB * 3 * EMB];
__device__ __nv_bfloat16 g_W1T [(size_t)FFN * 3 * EMB];
__device__ __nv_bfloat16 g_W2T [(size_t)EMB * 3 * FFN];

__device__ __forceinline__ float gelu_exact(float x) {
    return 0.5f * x * (1.0f + erff(x * 0.70710678118654752f));
}

// ===================== low-level helpers ===================================
__device__ __forceinline__ uint32_t smem_u32(const void* p) {
    uint32_t a;
    asm("{ .reg .u64 t; cvta.to.shared.u64 t, %1; cvt.u32.u64 %0, t; }"
        : "=r"(a) : "l"(p));
    return a;
}
__device__ __forceinline__ void cp_async16(uint32_t saddr, const void* gptr) {
    asm volatile("cp.async.cg.shared.global [%0], [%1], 16;"
                 :: "r"(saddr), "l"(gptr));
}
#define CP_COMMIT() asm volatile("cp.async.commit_group;" ::: "memory")
#define CP_WAIT0()  asm volatile("cp.async.wait_group 0;" ::: "memory")

__device__ __forceinline__ void ldsm_x4(uint32_t& r0, uint32_t& r1,
                                        uint32_t& r2, uint32_t& r3, uint32_t a) {
    asm volatile("ldmatrix.sync.aligned.m8n8.x4.shared.b16 {%0,%1,%2,%3}, [%4];"
                 : "=r"(r0), "=r"(r1), "=r"(r2), "=r"(r3) : "r"(a));
}
__device__ __forceinline__ void mma_bf16(float* c, const uint32_t* a, const uint32_t* b) {
    asm volatile(
        "mma.sync.aligned.m16n8k16.row.col.f32.bf16.bf16.f32 "
        "{%0,%1,%2,%3}, {%4,%5,%6,%7}, {%8,%9}, {%0,%1,%2,%3};"
        : "+f"(c[0]), "+f"(c[1]), "+f"(c[2]), "+f"(c[3])
        : "r"(a[0]), "r"(a[1]), "r"(a[2]), "r"(a[3]), "r"(b[0]), "r"(b[1]));
}

// ===================== conversion kernels ==================================
__global__ __launch_bounds__(256)
void convert_split(const float* __restrict__ X, __nv_bfloat16* __restrict__ Y, int K)
{
    size_t i = (size_t)blockIdx.x * blockDim.x + threadIdx.x;   // over M*K/4
    int kq = K >> 2;
    size_t row = i / kq;
    int k = (int)(i - row * kq) << 2;
    float4 v = *(const float4*)(X + row * K + k);
    __nv_bfloat16 hx = __float2bfloat16(v.x), hy = __float2bfloat16(v.y);
    __nv_bfloat16 hz = __float2bfloat16(v.z), hw = __float2bfloat16(v.w);
    __nv_bfloat16 lx = __float2bfloat16(v.x - __bfloat162float(hx));
    __nv_bfloat16 ly = __float2bfloat16(v.y - __bfloat162float(hy));
    __nv_bfloat16 lz = __float2bfloat16(v.z - __bfloat162float(hz));
    __nv_bfloat16 lw = __float2bfloat16(v.w - __bfloat162float(hw));
    __nv_bfloat16* o = Y + row * (size_t)(3 * K);
    __nv_bfloat162 h01; h01.x = hx; h01.y = hy;
    __nv_bfloat162 h23; h23.x = hz; h23.y = hw;
    __nv_bfloat162 l01; l01.x = lx; l01.y = ly;
    __nv_bfloat162 l23; l23.x = lz; l23.y = lw;
    *(__nv_bfloat162*)(o + k)           = h01;
    *(__nv_bfloat162*)(o + k + 2)       = h23;
    *(__nv_bfloat162*)(o + K + k)       = h01;
    *(__nv_bfloat162*)(o + K + k + 2)   = h23;
    *(__nv_bfloat162*)(o + 2*K + k)     = l01;
    *(__nv_bfloat162*)(o + 2*K + k + 2) = l23;
}

__global__ __launch_bounds__(256)
void convert_w_t(const float* __restrict__ W, __nv_bfloat16* __restrict__ Wt, int K, int N)
{
    __shared__ float t[32][33];
    int k0 = blockIdx.x * 32, n0 = blockIdx.y * 32;
    int tx = threadIdx.x, ty = threadIdx.y;   // block (32, 8)
#pragma unroll
    for (int i = 0; i < 4; i++)
        t[ty + i * 8][tx] = W[(size_t)(k0 + ty + i * 8) * N + n0 + tx];
    __syncthreads();
#pragma unroll
    for (int i = 0; i < 4; i++) {
        int r = ty + i * 8;
        float v = t[tx][r];
        __nv_bfloat16 h = __float2bfloat16(v);
        __nv_bfloat16 l = __float2bfloat16(v - __bfloat162float(h));
        __nv_bfloat16* o = Wt + (size_t)(n0 + r) * (3 * K) + k0 + tx;
        o[0]     = h;
        o[K]     = l;
        o[2 * K] = h;
    }
}

// ===================== mma.sync GEMM =======================================
// C[M, Ncols] = act(A[M, Keff] @ Bm[Ncols, Keff]^T + bias), bf16 in, fp32 out.
#define GBM 128
#define GBN 128
#define GBK 32
#define KPAD 40   // halves per smem row (80B stride -> conflict-free ldmatrix)

__global__ __launch_bounds__(256)
void gemm_mma(const __nv_bfloat16* __restrict__ A, const __nv_bfloat16* __restrict__ Bm,
              const float* __restrict__ bias, float* __restrict__ C,
              int Ncols, int Keff, int act)
{
    __shared__ __nv_bfloat16 As[2][GBM][KPAD];
    __shared__ __nv_bfloat16 Bs[2][GBN][KPAD];

    const int tid = threadIdx.x;
    const int wid = tid >> 5, lid = tid & 31;
    const int wm = wid >> 2;          // 0..1  -> 64-row slab
    const int wn = wid & 3;           // 0..3  -> 32-col slab
    const int m0 = blockIdx.y * GBM, n0 = blockIdx.x * GBN;

    const uint32_t sA = smem_u32(&As[0][0][0]);
    const uint32_t sB = smem_u32(&Bs[0][0][0]);
    const uint32_t stageA = GBM * KPAD * 2;   // bytes per stage
    const uint32_t stageB = GBN * KPAD * 2;

    float acc[4][4][4];
#pragma unroll
    for (int i = 0; i < 4; i++)
#pragma unroll
        for (int j = 0; j < 4; j++)
#pragma unroll
            for (int k = 0; k < 4; k++) acc[i][j][k] = 0.f;

    // per-thread load slots: chunks tid and tid+256 of 512 (A), same for B
    const int ra0 = tid >> 2,          ka0 = (tid & 3) << 3;
    const int ra1 = (tid + 256) >> 2,  ka1 = ((tid + 256) & 3) << 3;

    auto load_stage = [&](int c, int s) {
        int k0 = c * GBK;
        cp_async16(sA + s * stageA + (ra0 * KPAD + ka0) * 2,
                   A + (size_t)(m0 + ra0) * Keff + k0 + ka0);
        cp_async16(sA + s * stageA + (ra1 * KPAD + ka1) * 2,
                   A + (size_t)(m0 + ra1) * Keff + k0 + ka1);
        cp_async16(sB + s * stageB + (ra0 * KPAD + ka0) * 2,
                   Bm + (size_t)(n0 + ra0) * Keff + k0 + ka0);
        cp_async16(sB + s * stageB + (ra1 * KPAD + ka1) * 2,
                   Bm + (size_t)(n0 + ra1) * Keff + k0 + ka1);
    };

    const int nc = Keff / GBK;

    load_stage(0, 0);
    CP_COMMIT();

    for (int c = 0; c < nc; c++) {
        CP_WAIT0();
        __syncthreads();
        if (c + 1 < nc) { load_stage(c + 1, (c + 1) & 1); CP_COMMIT(); }

        const int s = c & 1;
#pragma unroll
        for (int ks = 0; ks < 2; ks++) {
            const int kk = ks * 16;
            uint32_t af[4][4], bf[4][2];
            // A fragments: 4 m-tiles of 16
#pragma unroll
            for (int mi = 0; mi < 4; mi++) {
                int row = wm * 64 + mi * 16 + (lid & 15);
                int col = kk + ((lid >> 4) << 3);
                ldsm_x4(af[mi][0], af[mi][1], af[mi][2], af[mi][3],
                        sA + s * stageA + (row * KPAD + col) * 2);
            }
            // B fragments: two x4 loads cover 4 n-tiles of 8
#pragma unroll
            for (int nb = 0; nb < 2; nb++) {
                int row = wn * 32 + nb * 16 + (lid & 7) + ((lid >> 4) << 3);
                int col = kk + (((lid >> 3) & 1) << 3);
                ldsm_x4(bf[nb * 2][0], bf[nb * 2][1], bf[nb * 2 + 1][0], bf[nb * 2 + 1][1],
                        sB + s * stageB + (row * KPAD + col) * 2);
            }
#pragma unroll
            for (int mi = 0; mi < 4; mi++)
#pragma unroll
                for (int ni = 0; ni < 4; ni++)
                    mma_bf16(acc[mi][ni], af[mi], bf[ni]);
        }
    }

    // epilogue: direct stores with fused bias (+gelu)
#pragma unroll
    for (int mi = 0; mi < 4; mi++) {
#pragma unroll
        for (int ni = 0; ni < 4; ni++) {
            int gr = m0 + wm * 64 + mi * 16 + (lid >> 2);
            int gc = n0 + wn * 32 + ni * 8 + ((lid & 3) << 1);
            float b0 = bias[gc], b1 = bias[gc + 1];
            float v0 = acc[mi][ni][0] + b0, v1 = acc[mi][ni][1] + b1;
            float v2 = acc[mi][ni][2] + b0, v3 = acc[mi][ni][3] + b1;
            if (act) { v0 = gelu_exact(v0); v1 = gelu_exact(v1);
                       v2 = gelu_exact(v2); v3 = gelu_exact(v3); }
            *(float2*)(C + (size_t)gr * Ncols + gc)       = make_float2(v0, v1);
            *(float2*)(C + (size_t)(gr + 8) * Ncols + gc) = make_float2(v2, v3);
        }
    }
}

// ===================== flash attention (unchanged) ==========================
#define BR 64
#define BC 64

__global__ __launch_bounds__(64)
void attn_kernel(const float* __restrict__ Q, const float* __restrict__ K,
                 const float* __restrict__ V, const float* __restrict__ bias,
                 float* __restrict__ O)
{
    __shared__ float Ks[BC][HD];
    __shared__ float Vs[BC][HD];
    __shared__ float Bsm[BC][BR];

    const int bh = blockIdx.y;
    const int b  = bh / HEADS;
    const int h  = bh % HEADS;
    const int q0 = blockIdx.x * BR;
    const int t  = threadIdx.x;

    const float* qptr = Q + ((size_t)b * SEQ + q0 + t) * EMB + h * HD;
    float q[HD], o[HD];
#pragma unroll
    for (int d = 0; d < HD; d++) { q[d] = qptr[d] * 0.125f; o[d] = 0.f; }

    float m = -1e30f, l = 0.f;

    for (int k0 = 0; k0 < SEQ; k0 += BC) {
        __syncthreads();
        for (int i = t; i < BC * HD / 4; i += BR) {
            int r = i / (HD / 4);
            int c = i % (HD / 4);
            const float4* kp = (const float4*)(K + ((size_t)b * SEQ + k0 + r) * EMB + h * HD);
            const float4* vp = (const float4*)(V + ((size_t)b * SEQ + k0 + r) * EMB + h * HD);
            ((float4*)Ks[r])[c] = kp[c];
            ((float4*)Vs[r])[c] = vp[c];
        }
        for (int i = t; i < BR * BC / 4; i += BR) {
            int r = i / (BC / 4);
            int c = (i % (BC / 4)) * 4;
            float4 v = *(const float4*)(bias + (size_t)(q0 + r) * SEQ + k0 + c);
            Bsm[c + 0][r] = v.x; Bsm[c + 1][r] = v.y;
            Bsm[c + 2][r] = v.z; Bsm[c + 3][r] = v.w;
        }
        __syncthreads();

        float mnew = m;
#pragma unroll 2
        for (int j = 0; j < BC; j++) {
            float acc = Bsm[j][t];
#pragma unroll
            for (int d = 0; d < HD; d++) acc += q[d] * Ks[j][d];
            Bsm[j][t] = acc;
            mnew = fmaxf(mnew, acc);
        }

        float corr = __expf(m - mnew);
        m = mnew;
        l *= corr;
#pragma unroll
        for (int d = 0; d < HD; d++) o[d] *= corr;

#pragma unroll 2
        for (int j = 0; j < BC; j++) {
            float p = __expf(Bsm[j][t] - m);
            l += p;
#pragma unroll
            for (int d = 0; d < HD; d++) o[d] += p * Vs[j][d];
        }
    }

    float inv = 1.f / l;
    float* op = O + ((size_t)b * SEQ + q0 + t) * EMB + h * HD;
#pragma unroll
    for (int d = 0; d < HD; d++) op[d] = o[d] * inv;
}

// ===================== fused residual add + LayerNorm =======================
__global__ __launch_bounds__(256)
void add_ln_kernel(const float* __restrict__ X, const float* __restrict__ R,
                   const float* __restrict__ w, const float* __restrict__ bias,
                   float* __restrict__ Y)
{
    __shared__ float red[32];
    const int row = blockIdx.x;
    const int tid = threadIdx.x;
    const float* xr = X + (size_t)row * EMB;
    const float* rr = R + (size_t)row * EMB;

    float v[4];
    float s = 0.f;
#pragma unroll
    for (int i = 0; i < 4; i++) {
        int c = i * 256 + tid;
        v[i] = xr[c] + rr[c];
        s += v[i];
    }
#pragma unroll
    for (int o = 16; o; o >>= 1) s += __shfl_xor_sync(0xffffffffu, s, o);
    if ((tid & 31) == 0) red[tid >> 5] = s;
    __syncthreads();
    if (tid < 32) {
        float r = (tid < 8) ? red[tid] : 0.f;
#pragma unroll
        for (int o = 4; o; o >>= 1) r += __shfl_xor_sync(0xffffffffu, r, o);
        if (tid == 0) red[0] = r;
    }
    __syncthreads();
    const float mu = red[0] * (1.0f / EMB);

    float vs = 0.f;
#pragma unroll
    for (int i = 0; i < 4; i++) {
        float d = v[i] - mu;
        vs += d * d;
    }
#pragma unroll
    for (int o = 16; o; o >>= 1) vs += __shfl_xor_sync(0xffffffffu, vs, o);
    __syncthreads();
    if ((tid & 31) == 0) red[tid >> 5] = vs;
    __syncthreads();
    if (tid < 32) {
        float r = (tid < 8) ? red[tid] : 0.f;
#pragma unroll
        for (int o = 4; o; o >>= 1) r += __shfl_xor_sync(0xffffffffu, r, o);
        if (tid == 0) red[0] = r;
    }
    __syncthreads();
    const float inv = rsqrtf(red[0] * (1.0f / EMB) + 1e-5f);

#pragma unroll
    for (int i = 0; i < 4; i++) {
        int c = i * 256 + tid;
        Y[(size_t)row * EMB + c] = (v[i] - mu) * inv * w[c] + bias[c];
    }
}

// ===================== launch ==============================================
template <typename T>
static T* symaddr(const void* s) {
    void* p = nullptr;
    cudaGetSymbolAddress(&p, s);
    return (T*)p;
}

extern "C" void kernel_launch(void* const* d_in, const int* in_sizes, int n_in,
                              void* d_out, int out_size)
{
    (void)in_sizes; (void)n_in; (void)out_size;
    const float* x    = (const float*)d_in[0];
    const float* ab   = (const float*)d_in[1];
    const float* Wq   = (const float*)d_in[2];
    const float* bq   = (const float*)d_in[3];
    const float* WaK  = (const float*)d_in[4];
    const float* baK  = (const float*)d_in[5];
    const float* WbK  = (const float*)d_in[6];
    const float* bbK  = (const float*)d_in[7];
    const float* WaV  = (const float*)d_in[8];
    const float* baV  = (const float*)d_in[9];
    const float* WbV  = (const float*)d_in[10];
    const float* bbV  = (const float*)d_in[11];
    const float* Wo   = (const float*)d_in[12];
    const float* bo   = (const float*)d_in[13];
    const float* W1   = (const float*)d_in[14];
    const float* b1   = (const float*)d_in[15];
    const float* W2   = (const float*)d_in[16];
    const float* b2   = (const float*)d_in[17];
    const float* ln1w = (const float*)d_in[18];
    const float* ln1b = (const float*)d_in[19];
    const float* ln2w = (const float*)d_in[20];
    const float* ln2b = (const float*)d_in[21];
    float* out = (float*)d_out;

    float* Q  = symaddr<float>(g_Q);  float* Ka = symaddr<float>(g_Ka);
    float* K  = symaddr<float>(g_K);  float* Va = symaddr<float>(g_Va);
    float* V  = symaddr<float>(g_V);  float* At = symaddr<float>(g_At);
    float* AO = symaddr<float>(g_AO); float* H  = symaddr<float>(g_H);
    float* F1 = symaddr<float>(g_F1); float* F2 = symaddr<float>(g_F2);

    __nv_bfloat16* Xb  = symaddr<__nv_bfloat16>(g_Xb);
    __nv_bfloat16* Kab = symaddr<__nv_bfloat16>(g_Kab);
    __nv_bfloat16* Vab = symaddr<__nv_bfloat16>(g_Vab);
    __nv_bfloat16* Atb = symaddr<__nv_bfloat16>(g_Atb);
    __nv_bfloat16* Hb  = symaddr<__nv_bfloat16>(g_Hb);
    __nv_bfloat16* F1b = symaddr<__nv_bfloat16>(g_F1b);
    __nv_bfloat16* WqT  = symaddr<__nv_bfloat16>(g_WqT);
    __nv_bfloat16* WaKT = symaddr<__nv_bfloat16>(g_WaKT);
    __nv_bfloat16* WbKT = symaddr<__nv_bfloat16>(g_WbKT);
    __nv_bfloat16* WaVT = symaddr<__nv_bfloat16>(g_WaVT);
    __nv_bfloat16* WbVT = symaddr<__nv_bfloat16>(g_WbVT);
    __nv_bfloat16* WoT  = symaddr<__nv_bfloat16>(g_WoT);
    __nv_bfloat16* W1T  = symaddr<__nv_bfloat16>(g_W1T);
    __nv_bfloat16* W2T  = symaddr<__nv_bfloat16>(g_W2T);

    dim3 tw(32, 8);
    auto launch_gemm = [](const __nv_bfloat16* A, const __nv_bfloat16* B,
                          const float* bias, float* C, int N, int Keff, int act) {
        gemm_mma<<<dim3(N / GBN, M_TOK / GBM), 256>>>(A, B, bias, C, N, Keff, act);
    };

    // weight prep
    convert_w_t<<<dim3(EMB / 32, EMB / 32), tw>>>(Wq,  WqT,  EMB, EMB);
    convert_w_t<<<dim3(EMB / 32, LAT / 32), tw>>>(WaK, WaKT, EMB, LAT);
    convert_w_t<<<dim3(LAT / 32, EMB / 32), tw>>>(WbK, WbKT, LAT, EMB);
    convert_w_t<<<dim3(EMB / 32, LAT / 32), tw>>>(WaV, WaVT, EMB, LAT);
    convert_w_t<<<dim3(LAT / 32, EMB / 32), tw>>>(WbV, WbVT, LAT, EMB);
    convert_w_t<<<dim3(EMB / 32, EMB / 32), tw>>>(Wo,  WoT,  EMB, EMB);
    convert_w_t<<<dim3(EMB / 32, FFN / 32), tw>>>(W1,  W1T,  EMB, FFN);
    convert_w_t<<<dim3(FFN / 32, EMB / 32), tw>>>(W2,  W2T,  FFN, EMB);

    // x -> bf16 split
    convert_split<<<M_TOK * EMB / 4 / 256, 256>>>(x, Xb, EMB);

    // projections
    launch_gemm(Xb, WqT,  bq,  Q,  EMB, 3 * EMB, 0);
    launch_gemm(Xb, WaKT, baK, Ka, LAT, 3 * EMB, 0);
    convert_split<<<M_TOK * LAT / 4 / 256, 256>>>(Ka, Kab, LAT);
    launch_gemm(Kab, WbKT, bbK, K, EMB, 3 * LAT, 0);
    launch_gemm(Xb, WaVT, baV, Va, LAT, 3 * EMB, 0);
    convert_split<<<M_TOK * LAT / 4 / 256, 256>>>(Va, Vab, LAT);
    launch_gemm(Vab, WbVT, bbV, V, EMB, 3 * LAT, 0);

    // attention
    attn_kernel<<<dim3(SEQ / BR, BATCH * HEADS), dim3(BR)>>>(Q, K, V, ab, At);

    // output projection + LN1
    convert_split<<<M_TOK * EMB / 4 / 256, 256>>>(At, Atb, EMB);
    launch_gemm(Atb, WoT, bo, AO, EMB, 3 * EMB, 0);
    add_ln_kernel<<<M_TOK, 256>>>(x, AO, ln1w, ln1b, H);

    // FFN + LN2
    convert_split<<<M_TOK * EMB / 4 / 256, 256>>>(H, Hb, EMB);
    launch_gemm(Hb, W1T, b1, F1, FFN, 3 * EMB, 1);
    convert_split<<<(int)((size_t)M_TOK * FFN / 4 / 256), 256>>>(F1, F1b, FFN);
    launch_gemm(F1b, W2T, b2, F2, EMB, 3 * FFN, 0);
    add_ln_kernel<<<M_TOK, 256>>>(H, F2, ln2w, ln2b, out);
}